// round 15
// baseline (speedup 1.0000x reference)
#include <cuda_runtime.h>
#include <cuda_fp16.h>
#include <cstdint>

typedef unsigned int u32;

// ---------------- problem constants ----------------
#define Bn 8
#define Nn 40962
#define Dn 40
#define Hn 512
#define DDn 32
#define KTOT 160               // 4 neighbors * 40
#define M_TOT (Bn*Nn)          // 327696
#define TMm 64                 // rows per CTA (4 CTAs/SM, 128 thr)
#define NTH 128
#define NBLK ((M_TOT + TMm - 1)/TMm)   // 5121
#define KA16 10                // GEMM1 k-atoms of 16 (160/16)

// ---------------- smem layout (u32 indices) ----------------
#define SM_Z    0              // Zf: [mb(4)][ka(10)][lane(32)][slot(4)] = 5120 u32
#define SM_B1   5120           // b1 as half2[256]
#define SM_B2   (SM_B1 + 256)
#define SM_BAS  (SM_B2 + 32)
#define SM_U32S (SM_BAS + 256)         // 5664
#define SMEM_BYTES (SM_U32S*4)         // 22656

// ---------------- helpers ----------------
__device__ __forceinline__ u32 pack2(float a, float b) {
    __half2 h = __floats2half2_rn(a, b);
    return *(u32*)&h;
}
// full-half2 gelu: u = x*(c1 + c2*x^2); h = x*(0.5*tanh(u)+0.5)
__device__ __forceinline__ u32 gelu2h(u32 xu) {
    __half2 xh = *(__half2*)&xu;
    const __half2 c1h = __float2half2_rn(0.7978845608028654f);
    const __half2 c2h = __float2half2_rn(0.0356774081f);
    const __half2 c05 = __float2half2_rn(0.5f);
    __half2 x2 = __hmul2(xh, xh);
    __half2 u  = __hmul2(xh, __hfma2(c2h, x2, c1h));
    u32 uu = *(u32*)&u;
    u32 tu; asm("tanh.approx.f16x2 %0, %1;" : "=r"(tu) : "r"(uu));
    __half2 t = *(__half2*)&tu;
    __half2 h = __hmul2(xh, __hfma2(t, c05, c05));
    return *(u32*)&h;
}

// m16n8k16 fp16 HMMA, f16 accum: D = 2 u32 (4 halves)
#define MMAH2(D, A, b0, b1) \
    asm("mma.sync.aligned.m16n8k16.row.col.f16.f16.f16.f16 " \
        "{%0,%1}, {%2,%3,%4,%5}, {%6,%7}, {%0,%1};" \
        : "+r"((D)[0]), "+r"((D)[1]) \
        : "r"((A)[0]), "r"((A)[1]), "r"((A)[2]), "r"((A)[3]), "r"(b0), "r"(b1))

// ---------------- global scratch ----------------
// W1 fp16 B-fragments: [ka16(10)][npair(32)][lane(32)] x uint4
__device__ uint4 g_W1h[KA16 * 32 * 32];
// W2 fp16 B-fragments: [gka16(32)][pa(2)][lane(32)] x uint4
__device__ uint4 g_W2h[32 * 2 * 32];
__device__ float g_xbuf[(size_t)M_TOT * Dn];

// prep: W1 -> fp16 B-frag order.
__global__ void prep_w1h(const float* __restrict__ W1) {
    int i = blockIdx.x * 256 + threadIdx.x;
    if (i >= KA16 * 32 * 32 * 4) return;
    int q    = i & 3;
    int lane = (i >> 2) & 31;
    int np   = (i >> 7) & 31;
    int ka   = i >> 12;
    int k = ka * 16 + (lane & 3) * 2 + (q & 1) * 8;
    int n = np * 16 + ((q >> 1) << 3) + (lane >> 2);
    float v0 = __ldg(&W1[(size_t)k * Hn + n]);
    float v1 = __ldg(&W1[(size_t)(k + 1) * Hn + n]);
    ((u32*)g_W1h)[i] = pack2(v0, v1);
}

// prep: W2 -> fp16 B-frag order (identity k mapping).
__global__ void prep_w2h(const float* __restrict__ W2) {
    int i = blockIdx.x * 256 + threadIdx.x;
    if (i >= 32 * 2 * 32 * 4) return;
    int q    = i & 3;
    int lane = (i >> 2) & 31;
    int pa   = (i >> 7) & 1;
    int gka  = i >> 8;
    int r = gka * 16 + (lane & 3) * 2 + (q & 1) * 8;
    int n = pa * 16 + ((q >> 1) << 3) + (lane >> 2);
    float v0 = __ldg(&W2[r * DDn + n]);
    float v1 = __ldg(&W2[(r + 1) * DDn + n]);
    ((u32*)g_W2h)[i] = pack2(v0, v1);
}

// ---------------- fused Euler step ----------------
__global__ void __launch_bounds__(NTH, 4)
step_kernel(const float* __restrict__ src, float* __restrict__ dst,
            const int* __restrict__ index,
            const uint4* __restrict__ W1h, const uint4* __restrict__ W2h,
            const float* __restrict__ b1, const float* __restrict__ b2)
{
    extern __shared__ u32 smu[];
    u32*   Zu   = smu;                   // fp16 A-frags: [mb(4)][ka(10)][lane(32)][slot(4)]
    u32*   b1hs = smu + SM_B1;           // b1 as half2[256]
    float* b2s  = (float*)(smu + SM_B2);
    int*   bas  = (int*)(smu + SM_BAS);
    u32*   redu = smu;                   // reduction scratch reuses Zf after GEMMs

    const int tid  = threadIdx.x;
    const int lane = tid & 31;
    const int wn   = tid >> 5;   // warp = N slice (0..3): 64 cols per 256-chunk
    const int m0   = blockIdx.x * TMm;
    const int rows_valid = min(TMm, M_TOT - m0);

    // gather bases (element offsets; 64 rows x 4 neighbors = 256, 2 per thread)
    #pragma unroll
    for (int i = tid; i < TMm * 4; i += NTH) {
        int r = i >> 2, k = i & 3;
        int base = 0;
        if (r < rows_valid) {
            int m = m0 + r, b = m / Nn, n = m - b * Nn;
            base = (b * Nn + __ldg(&index[n * 4 + k])) * Dn;
        }
        bas[i] = base;
    }
    // b1 -> half2 pairs in smem
    {
        float4 v = __ldg(((const float4*)b1) + tid);
        b1hs[tid * 2]     = pack2(v.x, v.y);
        b1hs[tid * 2 + 1] = pack2(v.z, v.w);
    }
    if (tid < 8) ((float4*)b2s)[tid] = __ldg(((const float4*)b2) + tid);
    __syncthreads();

    // ---- gather Z -> fp16 A-fragment layout (d4-major, 2 batches of MLP=10) ----
    #pragma unroll 1
    for (int bb = 0; bb < 2; ++bb) {
        float4 gv[10];
        int rka[10], d4a[10];
        #pragma unroll
        for (int j = 0; j < 10; ++j) {
            int t  = bb * 1280 + j * NTH + tid;   // 0..2559
            int rk = t / 10;
            int d4 = t - rk * 10;
            rka[j] = rk; d4a[j] = d4;
            gv[j] = __ldg((const float4*)(src + bas[rk] + d4 * 4));
        }
        #pragma unroll
        for (int j = 0; j < 10; ++j) {
            int rk = rka[j], d4 = d4a[j];
            int r  = rk >> 2, kn = rk & 3;
            int K  = kn * 40 + d4 * 4;
            int ka = K >> 4, kk = K & 15;
            int mb = r >> 4, rr = r & 15;
            int lane0 = ((rr & 7) << 2) + ((kk & 7) >> 1);
            int slot  = (rr >> 3) + ((kk >> 3) << 1);
            int base  = ((mb * KA16 + ka) * 32 + lane0) * 4 + slot;
            Zu[base]     = pack2(gv[j].x, gv[j].y);
            Zu[base + 4] = pack2(gv[j].z, gv[j].w);
        }
    }
    __syncthreads();

    const uint4* Za = (const uint4*)Zu;
    const int ccol = 2 * (lane & 3);

    // d2h persists across both chunks: [mb(4)][natom(4)][row_lo/hi] f16x2
    u32 d2h[4][4][2];
    #pragma unroll
    for (int m = 0; m < 4; ++m)
        #pragma unroll
        for (int a = 0; a < 4; ++a)
            { d2h[m][a][0] = 0u; d2h[m][a][1] = 0u; }

    // ---- 2 H-chunks of 256 cols; each warp owns 64 rows x 64 cols (mb=4, natoms=8) ----
    #pragma unroll 1
    for (int nc = 0; nc < 2; ++nc) {
        const int npA = nc * 16 + wn * 4;    // warp's 4 npairs
        u32 d1h[4][8][2];                    // [mb][natom][row_lo/hi] f16x2 accums
        #pragma unroll
        for (int m = 0; m < 4; ++m)
            #pragma unroll
            for (int a = 0; a < 8; ++a)
                { d1h[m][a][0] = 0u; d1h[m][a][1] = 0u; }

        #pragma unroll
        for (int ka = 0; ka < KA16; ++ka) {
            uint4 av[4];
            u32 a[4][4];
            #pragma unroll
            for (int m = 0; m < 4; ++m) {
                av[m] = Za[(m * KA16 + ka) * 32 + lane];
                a[m][0] = av[m].x; a[m][1] = av[m].y;
                a[m][2] = av[m].z; a[m][3] = av[m].w;
            }
            #pragma unroll
            for (int p = 0; p < 4; ++p) {
                uint4 bw = __ldg(W1h + (ka * 32 + npA + p) * 32 + lane);
                #pragma unroll
                for (int m = 0; m < 4; ++m) {
                    MMAH2(d1h[m][2*p],   a[m], bw.x, bw.y);
                    MMAH2(d1h[m][2*p+1], a[m], bw.z, bw.w);
                }
            }
        }

        // ---- bias + gelu (half2) + GEMM2 partial (f16 accum) ----
        const int colbase = nc * 256 + wn * 64;
        #pragma unroll
        for (int pg = 0; pg < 4; ++pg) {
            int cE = colbase + pg * 16 + ccol;     // even atom cols
            int cO = cE + 8;                       // odd atom cols
            u32 bE = b1hs[cE >> 1];
            u32 bO = b1hs[cO >> 1];
            __half2 bEh = *(__half2*)&bE, bOh = *(__half2*)&bO;
            u32 A2[4][4];
            #pragma unroll
            for (int m = 0; m < 4; ++m) {
                __half2 e0 = __hadd2(*(__half2*)&d1h[m][2*pg][0],   bEh);
                __half2 e1 = __hadd2(*(__half2*)&d1h[m][2*pg][1],   bEh);
                __half2 o0 = __hadd2(*(__half2*)&d1h[m][2*pg+1][0], bOh);
                __half2 o1 = __hadd2(*(__half2*)&d1h[m][2*pg+1][1], bOh);
                A2[m][0] = gelu2h(*(u32*)&e0);
                A2[m][1] = gelu2h(*(u32*)&e1);
                A2[m][2] = gelu2h(*(u32*)&o0);
                A2[m][3] = gelu2h(*(u32*)&o1);
            }
            int gka = nc * 16 + wn * 4 + pg;       // H 16-row block (0..31)
            #pragma unroll
            for (int pa = 0; pa < 2; ++pa) {
                uint4 w = __ldg(W2h + (gka * 2 + pa) * 32 + lane);
                #pragma unroll
                for (int m = 0; m < 4; ++m) {
                    MMAH2(d2h[m][2*pa],   A2[m], w.x, w.y);
                    MMAH2(d2h[m][2*pa+1], A2[m], w.z, w.w);
                }
            }
        }
    }

    __syncthreads();   // all Zf reads done before redu overwrites it

    // ---- cross-wn reduction: wn=1..3 store f16 partials, wn=0 sums in f32 ----
    if (wn >= 1) {
        u32* rp = redu + ((wn - 1) * 32 + lane) * 32;
        #pragma unroll
        for (int m = 0; m < 4; ++m)
            #pragma unroll
            for (int a = 0; a < 4; ++a) {
                rp[(m * 4 + a) * 2]     = d2h[m][a][0];
                rp[(m * 4 + a) * 2 + 1] = d2h[m][a][1];
            }
    }
    __syncthreads();

    if (wn == 0) {
        float d2[4][4][4];
        #pragma unroll
        for (int m = 0; m < 4; ++m)
            #pragma unroll
            for (int a = 0; a < 4; ++a) {
                float2 lo = __half22float2(*(__half2*)&d2h[m][a][0]);
                float2 hi = __half22float2(*(__half2*)&d2h[m][a][1]);
                d2[m][a][0] = lo.x; d2[m][a][1] = lo.y;
                d2[m][a][2] = hi.x; d2[m][a][3] = hi.y;
            }
        #pragma unroll
        for (int s = 0; s < 3; ++s) {
            const u32* rp = redu + (s * 32 + lane) * 32;
            #pragma unroll
            for (int m = 0; m < 4; ++m)
                #pragma unroll
                for (int a = 0; a < 4; ++a) {
                    float2 lo = __half22float2(*(__half2*)&rp[(m * 4 + a) * 2]);
                    float2 hi = __half22float2(*(__half2*)&rp[(m * 4 + a) * 2 + 1]);
                    d2[m][a][0] += lo.x; d2[m][a][1] += lo.y;
                    d2[m][a][2] += hi.x; d2[m][a][3] += hi.y;
                }
        }
        // epilogue: dst[row][c..c+1] = x + 0.1*(d2 + b2)
        #pragma unroll
        for (int m = 0; m < 4; ++m)
            #pragma unroll
            for (int rr = 0; rr < 2; ++rr) {
                int row = m * 16 + rr * 8 + (lane >> 2);
                if (row < rows_valid) {
                    size_t rb = (size_t)(m0 + row) * Dn;
                    #pragma unroll
                    for (int a = 0; a < 4; ++a) {
                        int c = a * 8 + ccol;
                        float2 xv = __ldg((const float2*)(src + rb + c));
                        float2 ov;
                        ov.x = xv.x + 0.1f * (d2[m][a][rr*2]     + b2s[c]);
                        ov.y = xv.y + 0.1f * (d2[m][a][rr*2 + 1] + b2s[c+1]);
                        *(float2*)(dst + rb + c) = ov;
                    }
                }
            }
    } else if (wn == 1) {
        // static dims 32..39 (unchanged by Euler step); 64 rows, 2 per lane
        #pragma unroll
        for (int h = 0; h < 2; ++h) {
            int row = h * 32 + lane;
            if (row < rows_valid) {
                size_t rb = (size_t)(m0 + row) * Dn;
                float4 s0 = __ldg((const float4*)(src + rb + 32));
                float4 s1 = __ldg((const float4*)(src + rb + 36));
                *(float4*)(dst + rb + 32) = s0;
                *(float4*)(dst + rb + 36) = s1;
            }
        }
    }
}

extern "C" void kernel_launch(void* const* d_in, const int* in_sizes, int n_in,
                              void* d_out, int out_size)
{
    const float* x     = (const float*)d_in[0];
    const int*   index = (const int*)  d_in[1];
    const float* W1    = (const float*)d_in[2];
    const float* b1    = (const float*)d_in[3];
    const float* W2    = (const float*)d_in[4];
    const float* b2    = (const float*)d_in[5];
    float* out = (float*)d_out;

    float* buf = nullptr;
    uint4 *w1h = nullptr, *w2h = nullptr;
    cudaGetSymbolAddress((void**)&buf, g_xbuf);
    cudaGetSymbolAddress((void**)&w1h, g_W1h);
    cudaGetSymbolAddress((void**)&w2h, g_W2h);

    cudaFuncSetAttribute(step_kernel, cudaFuncAttributeMaxDynamicSharedMemorySize, SMEM_BYTES);

    prep_w1h<<<(KA16*32*32*4 + 255)/256, 256>>>(W1);
    prep_w2h<<<(32*2*32*4 + 255)/256, 256>>>(W2);

    dim3 grid(NBLK), block(NTH);
    step_kernel<<<grid, block, SMEM_BYTES>>>(x,   buf, index, w1h, w2h, b1, b2);
    step_kernel<<<grid, block, SMEM_BYTES>>>(buf, out, index, w1h, w2h, b1, b2);
    step_kernel<<<grid, block, SMEM_BYTES>>>(out, buf, index, w1h, w2h, b1, b2);
    step_kernel<<<grid, block, SMEM_BYTES>>>(buf, out, index, w1h, w2h, b1, b2);
}

// round 16
// speedup vs baseline: 1.3000x; 1.3000x over previous
#include <cuda_runtime.h>
#include <cuda_fp16.h>
#include <cstdint>

typedef unsigned int u32;

// ---------------- problem constants ----------------
#define Bn 8
#define Nn 40962
#define Dn 40
#define Hn 512
#define DDn 32
#define KTOT 160               // 4 neighbors * 40
#define M_TOT (Bn*Nn)          // 327696
#define TMm 64                 // rows per CTA (4 CTAs/SM, 128 thr)
#define NTH 128
#define NBLK ((M_TOT + TMm - 1)/TMm)   // 5121
#define KA16 10                // GEMM1 k-atoms of 16 (160/16)

// ---------------- smem layout (u32 indices) ----------------
#define SM_Z    0              // Zf: [mb(4)][ka(10)][lane(32)][slot(4)] = 5120 u32 (redu reuses)
#define SM_ST   5120           // d2h chunk-0 stash: [idx(32)][tid(128)] = 4096 u32
#define SM_B1   9216           // b1 as half2[256]
#define SM_B2   (SM_B1 + 256)
#define SM_BAS  (SM_B2 + 32)
#define SM_U32S (SM_BAS + 256)         // 9760
#define SMEM_BYTES (SM_U32S*4)         // 39040

// ---------------- helpers ----------------
__device__ __forceinline__ u32 pack2(float a, float b) {
    __half2 h = __floats2half2_rn(a, b);
    return *(u32*)&h;
}
// full-half2 gelu: u = x*(c1 + c2*x^2); h = x*(0.5*tanh(u)+0.5)
__device__ __forceinline__ u32 gelu2h(u32 xu) {
    __half2 xh = *(__half2*)&xu;
    const __half2 c1h = __float2half2_rn(0.7978845608028654f);
    const __half2 c2h = __float2half2_rn(0.0356774081f);
    const __half2 c05 = __float2half2_rn(0.5f);
    __half2 x2 = __hmul2(xh, xh);
    __half2 u  = __hmul2(xh, __hfma2(c2h, x2, c1h));
    u32 uu = *(u32*)&u;
    u32 tu; asm("tanh.approx.f16x2 %0, %1;" : "=r"(tu) : "r"(uu));
    __half2 t = *(__half2*)&tu;
    __half2 h = __hmul2(xh, __hfma2(t, c05, c05));
    return *(u32*)&h;
}

// m16n8k16 fp16 HMMA, f16 accum: D = 2 u32 (4 halves)
#define MMAH2(D, A, b0, b1) \
    asm("mma.sync.aligned.m16n8k16.row.col.f16.f16.f16.f16 " \
        "{%0,%1}, {%2,%3,%4,%5}, {%6,%7}, {%0,%1};" \
        : "+r"((D)[0]), "+r"((D)[1]) \
        : "r"((A)[0]), "r"((A)[1]), "r"((A)[2]), "r"((A)[3]), "r"(b0), "r"(b1))

// ---------------- global scratch ----------------
// W1 fp16 B-fragments: [ka16(10)][npair(32)][lane(32)] x uint4
__device__ uint4 g_W1h[KA16 * 32 * 32];
// W2 fp16 B-fragments: [gka16(32)][pa(2)][lane(32)] x uint4
__device__ uint4 g_W2h[32 * 2 * 32];
__device__ float g_xbuf[(size_t)M_TOT * Dn];

// prep: W1 -> fp16 B-frag order.
__global__ void prep_w1h(const float* __restrict__ W1) {
    int i = blockIdx.x * 256 + threadIdx.x;
    if (i >= KA16 * 32 * 32 * 4) return;
    int q    = i & 3;
    int lane = (i >> 2) & 31;
    int np   = (i >> 7) & 31;
    int ka   = i >> 12;
    int k = ka * 16 + (lane & 3) * 2 + (q & 1) * 8;
    int n = np * 16 + ((q >> 1) << 3) + (lane >> 2);
    float v0 = __ldg(&W1[(size_t)k * Hn + n]);
    float v1 = __ldg(&W1[(size_t)(k + 1) * Hn + n]);
    ((u32*)g_W1h)[i] = pack2(v0, v1);
}

// prep: W2 -> fp16 B-frag order (identity k mapping).
__global__ void prep_w2h(const float* __restrict__ W2) {
    int i = blockIdx.x * 256 + threadIdx.x;
    if (i >= 32 * 2 * 32 * 4) return;
    int q    = i & 3;
    int lane = (i >> 2) & 31;
    int pa   = (i >> 7) & 1;
    int gka  = i >> 8;
    int r = gka * 16 + (lane & 3) * 2 + (q & 1) * 8;
    int n = pa * 16 + ((q >> 1) << 3) + (lane >> 2);
    float v0 = __ldg(&W2[r * DDn + n]);
    float v1 = __ldg(&W2[(r + 1) * DDn + n]);
    ((u32*)g_W2h)[i] = pack2(v0, v1);
}

// ---------------- fused Euler step ----------------
__global__ void __launch_bounds__(NTH, 4)
step_kernel(const float* __restrict__ src, float* __restrict__ dst,
            const int* __restrict__ index,
            const uint4* __restrict__ W1h, const uint4* __restrict__ W2h,
            const float* __restrict__ b1, const float* __restrict__ b2)
{
    extern __shared__ u32 smu[];
    u32*   Zu   = smu;                   // fp16 A-frags: [mb(4)][ka(10)][lane(32)][slot(4)]
    u32*   st   = smu + SM_ST;           // d2h chunk-0 stash [idx(32)][tid(128)]
    u32*   b1hs = smu + SM_B1;           // b1 as half2[256]
    float* b2s  = (float*)(smu + SM_B2);
    int*   bas  = (int*)(smu + SM_BAS);
    u32*   redu = smu;                   // reduction scratch reuses Zf after GEMMs

    const int tid  = threadIdx.x;
    const int lane = tid & 31;
    const int wn   = tid >> 5;   // warp = N slice (0..3): 64 cols per 256-chunk
    const int m0   = blockIdx.x * TMm;
    const int rows_valid = min(TMm, M_TOT - m0);

    // gather bases (element offsets; 64 rows x 4 neighbors = 256, 2 per thread)
    #pragma unroll
    for (int i = tid; i < TMm * 4; i += NTH) {
        int r = i >> 2, k = i & 3;
        int base = 0;
        if (r < rows_valid) {
            int m = m0 + r, b = m / Nn, n = m - b * Nn;
            base = (b * Nn + __ldg(&index[n * 4 + k])) * Dn;
        }
        bas[i] = base;
    }
    // b1 -> half2 pairs in smem
    {
        float4 v = __ldg(((const float4*)b1) + tid);
        b1hs[tid * 2]     = pack2(v.x, v.y);
        b1hs[tid * 2 + 1] = pack2(v.z, v.w);
    }
    if (tid < 8) ((float4*)b2s)[tid] = __ldg(((const float4*)b2) + tid);
    __syncthreads();

    // ---- gather Z -> fp16 A-fragment layout (d4-major, 2 batches of MLP=10) ----
    #pragma unroll 1
    for (int bb = 0; bb < 2; ++bb) {
        float4 gv[10];
        int rka[10], d4a[10];
        #pragma unroll
        for (int j = 0; j < 10; ++j) {
            int t  = bb * 1280 + j * NTH + tid;   // 0..2559
            int rk = t / 10;
            int d4 = t - rk * 10;
            rka[j] = rk; d4a[j] = d4;
            gv[j] = __ldg((const float4*)(src + bas[rk] + d4 * 4));
        }
        #pragma unroll
        for (int j = 0; j < 10; ++j) {
            int rk = rka[j], d4 = d4a[j];
            int r  = rk >> 2, kn = rk & 3;
            int K  = kn * 40 + d4 * 4;
            int ka = K >> 4, kk = K & 15;
            int mb = r >> 4, rr = r & 15;
            int lane0 = ((rr & 7) << 2) + ((kk & 7) >> 1);
            int slot  = (rr >> 3) + ((kk >> 3) << 1);
            int base  = ((mb * KA16 + ka) * 32 + lane0) * 4 + slot;
            Zu[base]     = pack2(gv[j].x, gv[j].y);
            Zu[base + 4] = pack2(gv[j].z, gv[j].w);
        }
    }
    __syncthreads();

    const uint4* Za = (const uint4*)Zu;
    const int ccol = 2 * (lane & 3);

    // d2h: per-chunk accumulators; chunk 0 result stashed in smem (thread-private,
    // no barrier needed) so the GEMM1 mainloop never carries them -> reg slack.
    u32 d2h[4][4][2];

    // ---- 2 H-chunks of 256 cols; each warp owns 64 rows x 64 cols (mb=4, natoms=8) ----
    #pragma unroll 1
    for (int nc = 0; nc < 2; ++nc) {
        const int npA = nc * 16 + wn * 4;    // warp's 4 npairs
        u32 d1h[4][8][2];                    // [mb][natom][row_lo/hi] f16x2 accums
        #pragma unroll
        for (int m = 0; m < 4; ++m)
            #pragma unroll
            for (int a = 0; a < 8; ++a)
                { d1h[m][a][0] = 0u; d1h[m][a][1] = 0u; }

        #pragma unroll
        for (int ka = 0; ka < KA16; ++ka) {
            uint4 av[4];
            u32 a[4][4];
            #pragma unroll
            for (int m = 0; m < 4; ++m) {
                av[m] = Za[(m * KA16 + ka) * 32 + lane];
                a[m][0] = av[m].x; a[m][1] = av[m].y;
                a[m][2] = av[m].z; a[m][3] = av[m].w;
            }
            #pragma unroll
            for (int p = 0; p < 4; ++p) {
                uint4 bw = __ldg(W1h + (ka * 32 + npA + p) * 32 + lane);
                #pragma unroll
                for (int m = 0; m < 4; ++m) {
                    MMAH2(d1h[m][2*p],   a[m], bw.x, bw.y);
                    MMAH2(d1h[m][2*p+1], a[m], bw.z, bw.w);
                }
            }
        }

        // ---- bias + gelu (half2) + GEMM2 partial (f16 accum, fresh per chunk) ----
        #pragma unroll
        for (int m = 0; m < 4; ++m)
            #pragma unroll
            for (int a = 0; a < 4; ++a)
                { d2h[m][a][0] = 0u; d2h[m][a][1] = 0u; }

        const int colbase = nc * 256 + wn * 64;
        #pragma unroll
        for (int pg = 0; pg < 4; ++pg) {
            int cE = colbase + pg * 16 + ccol;     // even atom cols
            int cO = cE + 8;                       // odd atom cols
            u32 bE = b1hs[cE >> 1];
            u32 bO = b1hs[cO >> 1];
            __half2 bEh = *(__half2*)&bE, bOh = *(__half2*)&bO;
            u32 A2[4][4];
            #pragma unroll
            for (int m = 0; m < 4; ++m) {
                __half2 e0 = __hadd2(*(__half2*)&d1h[m][2*pg][0],   bEh);
                __half2 e1 = __hadd2(*(__half2*)&d1h[m][2*pg][1],   bEh);
                __half2 o0 = __hadd2(*(__half2*)&d1h[m][2*pg+1][0], bOh);
                __half2 o1 = __hadd2(*(__half2*)&d1h[m][2*pg+1][1], bOh);
                A2[m][0] = gelu2h(*(u32*)&e0);
                A2[m][1] = gelu2h(*(u32*)&e1);
                A2[m][2] = gelu2h(*(u32*)&o0);
                A2[m][3] = gelu2h(*(u32*)&o1);
            }
            int gka = nc * 16 + wn * 4 + pg;       // H 16-row block (0..31)
            #pragma unroll
            for (int pa = 0; pa < 2; ++pa) {
                uint4 w = __ldg(W2h + (gka * 2 + pa) * 32 + lane);
                #pragma unroll
                for (int m = 0; m < 4; ++m) {
                    MMAH2(d2h[m][2*pa],   A2[m], w.x, w.y);
                    MMAH2(d2h[m][2*pa+1], A2[m], w.z, w.w);
                }
            }
        }

        // chunk 0: stash d2h in thread-private smem slot (lane-contiguous, no conflicts)
        if (nc == 0) {
            #pragma unroll
            for (int m = 0; m < 4; ++m)
                #pragma unroll
                for (int a = 0; a < 4; ++a) {
                    st[((m * 4 + a) * 2)     * NTH + tid] = d2h[m][a][0];
                    st[((m * 4 + a) * 2 + 1) * NTH + tid] = d2h[m][a][1];
                }
        }
    }

    __syncthreads();   // all Zf reads done before redu overwrites it

    // ---- cross-wn reduction: wn=1..3 store chunk-1 f16 partials; wn=0 sums in f32 ----
    if (wn >= 1) {
        u32* rp = redu + ((wn - 1) * 32 + lane) * 32;
        #pragma unroll
        for (int m = 0; m < 4; ++m)
            #pragma unroll
            for (int a = 0; a < 4; ++a) {
                rp[(m * 4 + a) * 2]     = d2h[m][a][0];
                rp[(m * 4 + a) * 2 + 1] = d2h[m][a][1];
            }
    }
    __syncthreads();

    if (wn == 0) {
        float d2[4][4][4];
        // own chunk 1 (regs) + own chunk 0 (stash)
        #pragma unroll
        for (int m = 0; m < 4; ++m)
            #pragma unroll
            for (int a = 0; a < 4; ++a) {
                float2 lo = __half22float2(*(__half2*)&d2h[m][a][0]);
                float2 hi = __half22float2(*(__half2*)&d2h[m][a][1]);
                u32 s0 = st[((m * 4 + a) * 2)     * NTH + tid];
                u32 s1 = st[((m * 4 + a) * 2 + 1) * NTH + tid];
                float2 slo = __half22float2(*(__half2*)&s0);
                float2 shi = __half22float2(*(__half2*)&s1);
                d2[m][a][0] = lo.x + slo.x; d2[m][a][1] = lo.y + slo.y;
                d2[m][a][2] = hi.x + shi.x; d2[m][a][3] = hi.y + shi.y;
            }
        // other warps: chunk 1 via redu, chunk 0 via their stash slots
        #pragma unroll
        for (int s = 0; s < 3; ++s) {
            const u32* rp = redu + (s * 32 + lane) * 32;
            int otid = (s + 1) * 32 + lane;
            #pragma unroll
            for (int m = 0; m < 4; ++m)
                #pragma unroll
                for (int a = 0; a < 4; ++a) {
                    float2 lo = __half22float2(*(__half2*)&rp[(m * 4 + a) * 2]);
                    float2 hi = __half22float2(*(__half2*)&rp[(m * 4 + a) * 2 + 1]);
                    u32 s0 = st[((m * 4 + a) * 2)     * NTH + otid];
                    u32 s1 = st[((m * 4 + a) * 2 + 1) * NTH + otid];
                    float2 slo = __half22float2(*(__half2*)&s0);
                    float2 shi = __half22float2(*(__half2*)&s1);
                    d2[m][a][0] += lo.x + slo.x; d2[m][a][1] += lo.y + slo.y;
                    d2[m][a][2] += hi.x + shi.x; d2[m][a][3] += hi.y + shi.y;
                }
        }
        // epilogue: dst[row][c..c+1] = x + 0.1*(d2 + b2)
        #pragma unroll
        for (int m = 0; m < 4; ++m)
            #pragma unroll
            for (int rr = 0; rr < 2; ++rr) {
                int row = m * 16 + rr * 8 + (lane >> 2);
                if (row < rows_valid) {
                    size_t rb = (size_t)(m0 + row) * Dn;
                    #pragma unroll
                    for (int a = 0; a < 4; ++a) {
                        int c = a * 8 + ccol;
                        float2 xv = __ldg((const float2*)(src + rb + c));
                        float2 ov;
                        ov.x = xv.x + 0.1f * (d2[m][a][rr*2]     + b2s[c]);
                        ov.y = xv.y + 0.1f * (d2[m][a][rr*2 + 1] + b2s[c+1]);
                        *(float2*)(dst + rb + c) = ov;
                    }
                }
            }
    } else if (wn == 1) {
        // static dims 32..39 (unchanged by Euler step); 64 rows, 2 per lane
        #pragma unroll
        for (int h = 0; h < 2; ++h) {
            int row = h * 32 + lane;
            if (row < rows_valid) {
                size_t rb = (size_t)(m0 + row) * Dn;
                float4 s0 = __ldg((const float4*)(src + rb + 32));
                float4 s1 = __ldg((const float4*)(src + rb + 36));
                *(float4*)(dst + rb + 32) = s0;
                *(float4*)(dst + rb + 36) = s1;
            }
        }
    }
}

extern "C" void kernel_launch(void* const* d_in, const int* in_sizes, int n_in,
                              void* d_out, int out_size)
{
    const float* x     = (const float*)d_in[0];
    const int*   index = (const int*)  d_in[1];
    const float* W1    = (const float*)d_in[2];
    const float* b1    = (const float*)d_in[3];
    const float* W2    = (const float*)d_in[4];
    const float* b2    = (const float*)d_in[5];
    float* out = (float*)d_out;

    float* buf = nullptr;
    uint4 *w1h = nullptr, *w2h = nullptr;
    cudaGetSymbolAddress((void**)&buf, g_xbuf);
    cudaGetSymbolAddress((void**)&w1h, g_W1h);
    cudaGetSymbolAddress((void**)&w2h, g_W2h);

    cudaFuncSetAttribute(step_kernel, cudaFuncAttributeMaxDynamicSharedMemorySize, SMEM_BYTES);

    prep_w1h<<<(KA16*32*32*4 + 255)/256, 256>>>(W1);
    prep_w2h<<<(32*2*32*4 + 255)/256, 256>>>(W2);

    dim3 grid(NBLK), block(NTH);
    step_kernel<<<grid, block, SMEM_BYTES>>>(x,   buf, index, w1h, w2h, b1, b2);
    step_kernel<<<grid, block, SMEM_BYTES>>>(buf, out, index, w1h, w2h, b1, b2);
    step_kernel<<<grid, block, SMEM_BYTES>>>(out, buf, index, w1h, w2h, b1, b2);
    step_kernel<<<grid, block, SMEM_BYTES>>>(buf, out, index, w1h, w2h, b1, b2);
}

// round 17
// speedup vs baseline: 1.4871x; 1.1439x over previous
#include <cuda_runtime.h>
#include <cuda_fp16.h>
#include <cstdint>

typedef unsigned int u32;

// ---------------- problem constants ----------------
#define Bn 8
#define Nn 40962
#define Dn 40
#define Hn 512
#define DDn 32
#define KTOT 160               // 4 neighbors * 40
#define M_TOT (Bn*Nn)          // 327696
#define TMm 32                 // rows per CTA (4 CTAs/SM)
#define NTH 128
#define NBLK ((M_TOT + TMm - 1)/TMm)   // 10241
#define KA16 10                // GEMM1 k-atoms of 16 (160/16)

// ---------------- smem layout (u32 indices) ----------------
// region A: max(Zf 2560 u32, redu 4*32*17=2176 u32) = 2560; keep 3456 slack
#define SM_Z    0
#define SM_B1   3456           // b1 as half2[256]
#define SM_B2   (SM_B1 + 512)
#define SM_BAS  (SM_B2 + 32)
#define SM_U32S (SM_BAS + 128)         // 4128
#define SMEM_BYTES (SM_U32S*4)         // 16512
#define REDST   17             // padded per-(src,lane) stride (conflict-free)

// ---------------- helpers ----------------
__device__ __forceinline__ u32 pack2(float a, float b) {
    __half2 h = __floats2half2_rn(a, b);
    return *(u32*)&h;
}
// full-half2 gelu: u = x*(c1 + c2*x^2); h = x*(0.5*tanh(u)+0.5)
__device__ __forceinline__ u32 gelu2h(u32 xu) {
    __half2 xh = *(__half2*)&xu;
    const __half2 c1h = __float2half2_rn(0.7978845608028654f);
    const __half2 c2h = __float2half2_rn(0.0356774081f);
    const __half2 c05 = __float2half2_rn(0.5f);
    __half2 x2 = __hmul2(xh, xh);
    __half2 u  = __hmul2(xh, __hfma2(c2h, x2, c1h));
    u32 uu = *(u32*)&u;
    u32 tu; asm("tanh.approx.f16x2 %0, %1;" : "=r"(tu) : "r"(uu));
    __half2 t = *(__half2*)&tu;
    __half2 h = __hmul2(xh, __hfma2(t, c05, c05));
    return *(u32*)&h;
}

// m16n8k16 fp16 HMMA, f16 accum: D = 2 u32 (4 halves)
#define MMAH2(D, A, b0, b1) \
    asm("mma.sync.aligned.m16n8k16.row.col.f16.f16.f16.f16 " \
        "{%0,%1}, {%2,%3,%4,%5}, {%6,%7}, {%0,%1};" \
        : "+r"((D)[0]), "+r"((D)[1]) \
        : "r"((A)[0]), "r"((A)[1]), "r"((A)[2]), "r"((A)[3]), "r"(b0), "r"(b1))

// ---------------- global scratch ----------------
// W1 fp16 B-fragments: [ka16(10)][npair(32)][lane(32)] x uint4
__device__ uint4 g_W1h[KA16 * 32 * 32];
// W2 fp16 B-fragments: [gka16(32)][pa(2)][lane(32)] x uint4
__device__ uint4 g_W2h[32 * 2 * 32];
__device__ float g_xbuf[(size_t)M_TOT * Dn];

// prep: W1 -> fp16 B-frag order.
__global__ void prep_w1h(const float* __restrict__ W1) {
    int i = blockIdx.x * 256 + threadIdx.x;
    if (i >= KA16 * 32 * 32 * 4) return;
    int q    = i & 3;
    int lane = (i >> 2) & 31;
    int np   = (i >> 7) & 31;
    int ka   = i >> 12;
    int k = ka * 16 + (lane & 3) * 2 + (q & 1) * 8;
    int n = np * 16 + ((q >> 1) << 3) + (lane >> 2);
    float v0 = __ldg(&W1[(size_t)k * Hn + n]);
    float v1 = __ldg(&W1[(size_t)(k + 1) * Hn + n]);
    ((u32*)g_W1h)[i] = pack2(v0, v1);
}

// prep: W2 -> fp16 B-frag order (identity k mapping).
__global__ void prep_w2h(const float* __restrict__ W2) {
    int i = blockIdx.x * 256 + threadIdx.x;
    if (i >= 32 * 2 * 32 * 4) return;
    int q    = i & 3;
    int lane = (i >> 2) & 31;
    int pa   = (i >> 7) & 1;
    int gka  = i >> 8;
    int r = gka * 16 + (lane & 3) * 2 + (q & 1) * 8;
    int n = pa * 16 + ((q >> 1) << 3) + (lane >> 2);
    float v0 = __ldg(&W2[r * DDn + n]);
    float v1 = __ldg(&W2[(r + 1) * DDn + n]);
    ((u32*)g_W2h)[i] = pack2(v0, v1);
}

// ---------------- fused Euler step ----------------
__global__ void __launch_bounds__(NTH, 4)
step_kernel(const float* __restrict__ src, float* __restrict__ dst,
            const int* __restrict__ index,
            const uint4* __restrict__ W1h, const uint4* __restrict__ W2h,
            const float* __restrict__ b1, const float* __restrict__ b2)
{
    extern __shared__ u32 smu[];
    u32*   Zu   = smu;                   // fp16 A-frags: [mb(2)][ka16(10)][lane(32)][slot(4)]
    u32*   b1hs = smu + SM_B1;           // b1 as half2[256]
    float* b2s  = (float*)(smu + SM_B2);
    int*   bas  = (int*)(smu + SM_BAS);
    u32*   redu = smu;                   // reduction slab reuses Zf: [(src*32+lane)*17 + idx]

    const int tid  = threadIdx.x;
    const int lane = tid & 31;
    const int wn   = tid >> 5;   // warp = N slice: 128-col slice of H (0..3)
    const int m0   = blockIdx.x * TMm;
    const int rows_valid = min(TMm, M_TOT - m0);

    // gather bases (element offsets; one per thread: 32 rows x 4 neighbors)
    {
        int r = tid >> 2, k = tid & 3;
        int base = 0;
        if (r < rows_valid) {
            int m = m0 + r, b = m / Nn, n = m - b * Nn;
            base = (b * Nn + __ldg(&index[n * 4 + k])) * Dn;
        }
        bas[tid] = base;
    }
    // b1 -> half2 pairs in smem
    {
        float4 v = __ldg(((const float4*)b1) + tid);
        b1hs[tid * 2]     = pack2(v.x, v.y);
        b1hs[tid * 2 + 1] = pack2(v.z, v.w);
    }
    if (tid < 8) ((float4*)b2s)[tid] = __ldg(((const float4*)b2) + tid);
    __syncthreads();

    // ---- gather Z -> fp16 A-fragment layout (d4-major, MLP=10) ----
    {
        float4 gv[10];
        int rka[10], d4a[10];
        #pragma unroll
        for (int j = 0; j < 10; ++j) {
            int t  = j * NTH + tid;          // 0..1279
            int rk = t / 10;
            int d4 = t - rk * 10;
            rka[j] = rk; d4a[j] = d4;
            gv[j] = __ldg((const float4*)(src + bas[rk] + d4 * 4));
        }
        #pragma unroll
        for (int j = 0; j < 10; ++j) {
            int rk = rka[j], d4 = d4a[j];
            int r  = rk >> 2, kn = rk & 3;
            int K  = kn * 40 + d4 * 4;
            int ka = K >> 4, kk = K & 15;
            int mb = r >> 4, rr = r & 15;
            int lane0 = ((rr & 7) << 2) + ((kk & 7) >> 1);
            int slot  = (rr >> 3) + ((kk >> 3) << 1);
            int base  = ((mb * KA16 + ka) * 32 + lane0) * 4 + slot;
            Zu[base]     = pack2(gv[j].x, gv[j].y);
            Zu[base + 4] = pack2(gv[j].z, gv[j].w);
        }
    }
    __syncthreads();

    const uint4* Za = (const uint4*)Zu;
    const int ccol = 2 * (lane & 3);
    const int npA  = wn * 8;      // warp's 8 npairs (128 H-cols)

    // ---- single-pass GEMM1: each warp 32 rows x 128 cols, f16 accum ----
    u32 d1h[2][16][2];            // [mb][natom][row_lo/row_hi] f16x2 accums
    #pragma unroll
    for (int m = 0; m < 2; ++m)
        #pragma unroll
        for (int a = 0; a < 16; ++a)
            { d1h[m][a][0] = 0u; d1h[m][a][1] = 0u; }

    #pragma unroll
    for (int ka = 0; ka < KA16; ++ka) {
        uint4 av0 = Za[(0 * KA16 + ka) * 32 + lane];
        uint4 av1 = Za[(1 * KA16 + ka) * 32 + lane];
        u32 a0[4] = {av0.x, av0.y, av0.z, av0.w};
        u32 a1[4] = {av1.x, av1.y, av1.z, av1.w};
        #pragma unroll
        for (int p = 0; p < 8; ++p) {
            uint4 bw = __ldg(W1h + (ka * 32 + npA + p) * 32 + lane);
            MMAH2(d1h[0][2*p],   a0, bw.x, bw.y);
            MMAH2(d1h[1][2*p],   a1, bw.x, bw.y);
            MMAH2(d1h[0][2*p+1], a0, bw.z, bw.w);
            MMAH2(d1h[1][2*p+1], a1, bw.z, bw.w);
        }
    }

    // ---- bias + gelu (half2) + GEMM2 partial (f16 accum) ----
    u32 d2h[2][4][2];             // [mb][natom][row_lo/row_hi] f16x2 accums
    #pragma unroll
    for (int m = 0; m < 2; ++m)
        #pragma unroll
        for (int a = 0; a < 4; ++a)
            { d2h[m][a][0] = 0u; d2h[m][a][1] = 0u; }

    #pragma unroll
    for (int pg = 0; pg < 8; ++pg) {
        int cE = wn * 128 + pg * 16 + ccol;    // even atom cols (2c,2c+1)
        int cO = cE + 8;                       // odd atom cols
        u32 bE = b1hs[cE >> 1];
        u32 bO = b1hs[cO >> 1];
        __half2 bEh = *(__half2*)&bE, bOh = *(__half2*)&bO;
        u32 A2[2][4];
        #pragma unroll
        for (int m = 0; m < 2; ++m) {
            __half2 e0 = __hadd2(*(__half2*)&d1h[m][2*pg][0],   bEh);
            __half2 e1 = __hadd2(*(__half2*)&d1h[m][2*pg][1],   bEh);
            __half2 o0 = __hadd2(*(__half2*)&d1h[m][2*pg+1][0], bOh);
            __half2 o1 = __hadd2(*(__half2*)&d1h[m][2*pg+1][1], bOh);
            A2[m][0] = gelu2h(*(u32*)&e0);
            A2[m][1] = gelu2h(*(u32*)&e1);
            A2[m][2] = gelu2h(*(u32*)&o0);
            A2[m][3] = gelu2h(*(u32*)&o1);
        }
        int gka = npA + pg;                    // H 16-row block (0..31)
        #pragma unroll
        for (int pa = 0; pa < 2; ++pa) {
            uint4 w = __ldg(W2h + (gka * 2 + pa) * 32 + lane);
            MMAH2(d2h[0][2*pa],   A2[0], w.x, w.y);
            MMAH2(d2h[1][2*pa],   A2[1], w.x, w.y);
            MMAH2(d2h[0][2*pa+1], A2[0], w.z, w.w);
            MMAH2(d2h[1][2*pa+1], A2[1], w.z, w.w);
        }
    }

    __syncthreads();   // all Zf reads done before redu overwrites it

    // ---- ALL warps store f16 partials to padded slab (banks distinct: stride 17) ----
    // d2h[m][a][rr] = half2 for (row m*16 + rr*8 + lane/4, cols a*8 + 2*(lane%4) + {0,1})
    {
        u32* rp = redu + (wn * 32 + lane) * REDST;
        #pragma unroll
        for (int m = 0; m < 2; ++m)
            #pragma unroll
            for (int a = 0; a < 4; ++a) {
                rp[(m * 4 + a) * 2]     = d2h[m][a][0];
                rp[(m * 4 + a) * 2 + 1] = d2h[m][a][1];
            }
    }
    __syncthreads();

    // ---- parallel reduce + epilogue: warp wn owns rows [wn*8, wn*8+8) ----
    // lane l: row r = wn*8 + l/4, col group cg = l%3... cg = l&3 -> cols cg*8..cg*8+7
    {
        int r  = wn * 8 + (lane >> 2);
        int cg = lane & 3;
        if (r < rows_valid) {
            int m  = r >> 4;
            int rr = (r >> 3) & 1;
            int lsd = (r & 7) * 4;           // lane_src base (jj added per pair)
            int idx = (m * 4 + cg) * 2 + rr; // u32 index within a source's 16
            float o[8];
            #pragma unroll
            for (int j = 0; j < 8; ++j) o[j] = 0.f;
            #pragma unroll
            for (int s = 0; s < 4; ++s) {
                #pragma unroll
                for (int jj = 0; jj < 4; ++jj) {
                    u32 v = redu[(s * 32 + lsd + jj) * REDST + idx];
                    float2 f = __half22float2(*(__half2*)&v);
                    o[2*jj]     += f.x;
                    o[2*jj + 1] += f.y;
                }
            }
            size_t rb = (size_t)(m0 + r) * Dn;
            const float4* xp = (const float4*)(src + rb + cg * 8);
            float4 x0 = __ldg(xp), x1 = __ldg(xp + 1);
            float4 bb0 = ((const float4*)b2s)[cg * 2];
            float4 bb1 = ((const float4*)b2s)[cg * 2 + 1];
            float4 w0, w1;
            w0.x = x0.x + 0.1f * (o[0] + bb0.x);
            w0.y = x0.y + 0.1f * (o[1] + bb0.y);
            w0.z = x0.z + 0.1f * (o[2] + bb0.z);
            w0.w = x0.w + 0.1f * (o[3] + bb0.w);
            w1.x = x1.x + 0.1f * (o[4] + bb1.x);
            w1.y = x1.y + 0.1f * (o[5] + bb1.y);
            w1.z = x1.z + 0.1f * (o[6] + bb1.z);
            w1.w = x1.w + 0.1f * (o[7] + bb1.w);
            float4* dp = (float4*)(dst + rb + cg * 8);
            dp[0] = w0;
            dp[1] = w1;
            if (cg == 3) {  // static dims 32..39 (unchanged by Euler step)
                float4 s0 = __ldg((const float4*)(src + rb + 32));
                float4 s1 = __ldg((const float4*)(src + rb + 36));
                *(float4*)(dst + rb + 32) = s0;
                *(float4*)(dst + rb + 36) = s1;
            }
        }
    }
}

extern "C" void kernel_launch(void* const* d_in, const int* in_sizes, int n_in,
                              void* d_out, int out_size)
{
    const float* x     = (const float*)d_in[0];
    const int*   index = (const int*)  d_in[1];
    const float* W1    = (const float*)d_in[2];
    const float* b1    = (const float*)d_in[3];
    const float* W2    = (const float*)d_in[4];
    const float* b2    = (const float*)d_in[5];
    float* out = (float*)d_out;

    float* buf = nullptr;
    uint4 *w1h = nullptr, *w2h = nullptr;
    cudaGetSymbolAddress((void**)&buf, g_xbuf);
    cudaGetSymbolAddress((void**)&w1h, g_W1h);
    cudaGetSymbolAddress((void**)&w2h, g_W2h);

    cudaFuncSetAttribute(step_kernel, cudaFuncAttributeMaxDynamicSharedMemorySize, SMEM_BYTES);

    prep_w1h<<<(KA16*32*32*4 + 255)/256, 256>>>(W1);
    prep_w2h<<<(32*2*32*4 + 255)/256, 256>>>(W2);

    dim3 grid(NBLK), block(NTH);
    step_kernel<<<grid, block, SMEM_BYTES>>>(x,   buf, index, w1h, w2h, b1, b2);
    step_kernel<<<grid, block, SMEM_BYTES>>>(buf, out, index, w1h, w2h, b1, b2);
    step_kernel<<<grid, block, SMEM_BYTES>>>(out, buf, index, w1h, w2h, b1, b2);
    step_kernel<<<grid, block, SMEM_BYTES>>>(buf, out, index, w1h, w2h, b1, b2);
}